// round 1
// baseline (speedup 1.0000x reference)
#include <cuda_runtime.h>

#define NB   4
#define SQL  2048
#define SKL  2048
#define DIM  512
#define RAD  128
#define NREL 257   // 2*RAD+1

// scratch for Q_rel[b,q,r] = Q[b,q,:] . rel_embeds[r,:]
__device__ float g_qrel[(size_t)NB * SQL * NREL];

// ---------------------------------------------------------------------------
// GEMM 1: g_qrel[M, NREL] = Q[M, DIM] * RE[NREL, DIM]^T,  M = NB*SQL
// 64x64 tile, BK=16, 256 threads, 4x4 microtile
// ---------------------------------------------------------------------------
__global__ void __launch_bounds__(256) gemm_qrel_kernel(const float* __restrict__ Q,
                                                        const float* __restrict__ RE) {
    __shared__ float As[64][17];
    __shared__ float Bs[64][17];
    const int tid = threadIdx.x;
    const int tx = tid & 15, ty = tid >> 4;
    const int m0 = blockIdx.x * 64;
    const int n0 = blockIdx.y * 64;
    const int lr = tid >> 2;          // 0..63
    const int lk = (tid & 3) << 2;    // 0,4,8,12

    float acc[4][4] = {};

    for (int k0 = 0; k0 < DIM; k0 += 16) {
        float4 a4 = *(const float4*)(Q + (size_t)(m0 + lr) * DIM + k0 + lk);
        As[lr][lk + 0] = a4.x; As[lr][lk + 1] = a4.y;
        As[lr][lk + 2] = a4.z; As[lr][lk + 3] = a4.w;

        float4 b4 = make_float4(0.f, 0.f, 0.f, 0.f);
        if (n0 + lr < NREL)
            b4 = *(const float4*)(RE + (size_t)(n0 + lr) * DIM + k0 + lk);
        Bs[lr][lk + 0] = b4.x; Bs[lr][lk + 1] = b4.y;
        Bs[lr][lk + 2] = b4.z; Bs[lr][lk + 3] = b4.w;
        __syncthreads();

        #pragma unroll
        for (int kk = 0; kk < 16; kk++) {
            float a[4], b[4];
            #pragma unroll
            for (int i = 0; i < 4; i++) a[i] = As[ty * 4 + i][kk];
            #pragma unroll
            for (int j = 0; j < 4; j++) b[j] = Bs[tx * 4 + j][kk];
            #pragma unroll
            for (int i = 0; i < 4; i++)
                #pragma unroll
                for (int j = 0; j < 4; j++)
                    acc[i][j] = fmaf(a[i], b[j], acc[i][j]);
        }
        __syncthreads();
    }

    #pragma unroll
    for (int i = 0; i < 4; i++) {
        const int gm = m0 + ty * 4 + i;
        #pragma unroll
        for (int j = 0; j < 4; j++) {
            const int gn = n0 + tx * 4 + j;
            if (gn < NREL) g_qrel[(size_t)gm * NREL + gn] = acc[i][j];
        }
    }
}

// ---------------------------------------------------------------------------
// GEMM 2: scores[b, q, k] = (Q[b,q,:] . K[b,k,:] + Q_rel[b,q, clip(k-q)+RAD]) / sqrt(DIM)
// Per-batch via blockIdx.z. 64x64 tile, BK=16.
// ---------------------------------------------------------------------------
__global__ void __launch_bounds__(256) gemm_scores_kernel(const float* __restrict__ Qg,
                                                          const float* __restrict__ Kg,
                                                          float* __restrict__ attn) {
    const int b = blockIdx.z;
    const float* A  = Qg + (size_t)b * SQL * DIM;
    const float* Bm = Kg + (size_t)b * SKL * DIM;
    float* C = attn + (size_t)b * SQL * SKL;

    __shared__ float As[64][17];
    __shared__ float Bs[64][17];
    const int tid = threadIdx.x;
    const int tx = tid & 15, ty = tid >> 4;
    const int m0 = blockIdx.x * 64;
    const int n0 = blockIdx.y * 64;
    const int lr = tid >> 2;
    const int lk = (tid & 3) << 2;

    float acc[4][4] = {};

    for (int k0 = 0; k0 < DIM; k0 += 16) {
        float4 a4 = *(const float4*)(A + (size_t)(m0 + lr) * DIM + k0 + lk);
        As[lr][lk + 0] = a4.x; As[lr][lk + 1] = a4.y;
        As[lr][lk + 2] = a4.z; As[lr][lk + 3] = a4.w;

        float4 b4 = *(const float4*)(Bm + (size_t)(n0 + lr) * DIM + k0 + lk);
        Bs[lr][lk + 0] = b4.x; Bs[lr][lk + 1] = b4.y;
        Bs[lr][lk + 2] = b4.z; Bs[lr][lk + 3] = b4.w;
        __syncthreads();

        #pragma unroll
        for (int kk = 0; kk < 16; kk++) {
            float a[4], bb[4];
            #pragma unroll
            for (int i = 0; i < 4; i++) a[i] = As[ty * 4 + i][kk];
            #pragma unroll
            for (int j = 0; j < 4; j++) bb[j] = Bs[tx * 4 + j][kk];
            #pragma unroll
            for (int i = 0; i < 4; i++)
                #pragma unroll
                for (int j = 0; j < 4; j++)
                    acc[i][j] = fmaf(a[i], bb[j], acc[i][j]);
        }
        __syncthreads();
    }

    const float inv_norm = 0.04419417382415922f;  // 1/sqrt(512)
    #pragma unroll
    for (int i = 0; i < 4; i++) {
        const int q = m0 + ty * 4 + i;
        const float* qrel_row = &g_qrel[((size_t)b * SQL + q) * NREL];
        #pragma unroll
        for (int j = 0; j < 4; j++) {
            const int kc = n0 + tx * 4 + j;
            int rel = kc - q;
            rel = max(-RAD, min(RAD, rel)) + RAD;
            C[(size_t)q * SKL + kc] = (acc[i][j] + qrel_row[rel]) * inv_norm;
        }
    }
}

// ---------------------------------------------------------------------------
// Row softmax over SKL=2048 columns. One block (256 threads) per row, 8 elems/thread.
// ---------------------------------------------------------------------------
__global__ void __launch_bounds__(256) softmax_rows_kernel(float* __restrict__ attn) {
    __shared__ float red[8];
    float* p = attn + (size_t)blockIdx.x * SKL;
    const int t = threadIdx.x;

    float v[8];
    float mx = -1e30f;
    #pragma unroll
    for (int i = 0; i < 8; i++) {
        v[i] = p[t + i * 256];
        mx = fmaxf(mx, v[i]);
    }
    #pragma unroll
    for (int o = 16; o > 0; o >>= 1) mx = fmaxf(mx, __shfl_xor_sync(0xffffffffu, mx, o));
    if ((t & 31) == 0) red[t >> 5] = mx;
    __syncthreads();
    float bmx = red[0];
    #pragma unroll
    for (int i = 1; i < 8; i++) bmx = fmaxf(bmx, red[i]);
    __syncthreads();

    float s = 0.f;
    #pragma unroll
    for (int i = 0; i < 8; i++) {
        v[i] = __expf(v[i] - bmx);
        s += v[i];
    }
    #pragma unroll
    for (int o = 16; o > 0; o >>= 1) s += __shfl_xor_sync(0xffffffffu, s, o);
    if ((t & 31) == 0) red[t >> 5] = s;
    __syncthreads();
    float tot = 0.f;
    #pragma unroll
    for (int i = 0; i < 8; i++) tot += red[i];
    const float inv = 1.0f / tot;

    #pragma unroll
    for (int i = 0; i < 8; i++) p[t + i * 256] = v[i] * inv;
}

// ---------------------------------------------------------------------------
// GEMM 3: Z[b, q, n] = sum_k attn[b,q,k] * V[b,k,n]   (NN GEMM, K = SKL)
// ---------------------------------------------------------------------------
__global__ void __launch_bounds__(256) gemm_av_kernel(const float* __restrict__ attn,
                                                      const float* __restrict__ Vg,
                                                      float* __restrict__ Z) {
    const int b = blockIdx.z;
    const float* A  = attn + (size_t)b * SQL * SKL;
    const float* Bp = Vg + (size_t)b * SKL * DIM;
    float* C = Z + (size_t)b * SQL * DIM;

    __shared__ float As[64][17];
    __shared__ float Bs[16][64];
    const int tid = threadIdx.x;
    const int tx = tid & 15, ty = tid >> 4;
    const int m0 = blockIdx.x * 64;
    const int n0 = blockIdx.y * 64;
    const int lr = tid >> 2;
    const int lk = (tid & 3) << 2;
    const int bk = tid >> 4;          // 0..15
    const int bn = (tid & 15) << 2;   // 0..60

    float acc[4][4] = {};

    for (int k0 = 0; k0 < SKL; k0 += 16) {
        float4 a4 = *(const float4*)(A + (size_t)(m0 + lr) * SKL + k0 + lk);
        As[lr][lk + 0] = a4.x; As[lr][lk + 1] = a4.y;
        As[lr][lk + 2] = a4.z; As[lr][lk + 3] = a4.w;

        float4 b4 = *(const float4*)(Bp + (size_t)(k0 + bk) * DIM + n0 + bn);
        *(float4*)&Bs[bk][bn] = b4;
        __syncthreads();

        #pragma unroll
        for (int kk = 0; kk < 16; kk++) {
            float a[4];
            #pragma unroll
            for (int i = 0; i < 4; i++) a[i] = As[ty * 4 + i][kk];
            float4 bv = *(const float4*)&Bs[kk][tx * 4];
            float bb[4] = {bv.x, bv.y, bv.z, bv.w};
            #pragma unroll
            for (int i = 0; i < 4; i++)
                #pragma unroll
                for (int j = 0; j < 4; j++)
                    acc[i][j] = fmaf(a[i], bb[j], acc[i][j]);
        }
        __syncthreads();
    }

    #pragma unroll
    for (int i = 0; i < 4; i++) {
        const int gm = m0 + ty * 4 + i;
        #pragma unroll
        for (int j = 0; j < 4; j++) {
            const int gn = n0 + tx * 4 + j;
            C[(size_t)gm * DIM + gn] = acc[i][j];
        }
    }
}

// ---------------------------------------------------------------------------
extern "C" void kernel_launch(void* const* d_in, const int* in_sizes, int n_in,
                              void* d_out, int out_size) {
    const float* Q  = (const float*)d_in[0];
    const float* K  = (const float*)d_in[1];
    const float* V  = (const float*)d_in[2];
    const float* RE = (const float*)d_in[3];

    float* attn = (float*)d_out;                                   // [NB, SQL, SKL]
    float* Z    = attn + (size_t)NB * SQL * SKL;                   // [NB, SQL, DIM]

    // 1) Q_rel = Q @ rel_embeds^T  -> g_qrel
    {
        dim3 grid((NB * SQL) / 64, (NREL + 63) / 64);
        gemm_qrel_kernel<<<grid, 256>>>(Q, RE);
    }
    // 2) scores = (Q@K^T + rel_shift) / sqrt(d)  -> attn region (raw)
    {
        dim3 grid(SQL / 64, SKL / 64, NB);
        gemm_scores_kernel<<<grid, 256>>>(Q, K, attn);
    }
    // 3) softmax rows in place
    {
        softmax_rows_kernel<<<NB * SQL, 256>>>(attn);
    }
    // 4) Z = attn @ V
    {
        dim3 grid(SQL / 64, DIM / 64, NB);
        gemm_av_kernel<<<grid, 256>>>(attn, V, Z);
    }
}

// round 2
// speedup vs baseline: 1.2575x; 1.2575x over previous
#include <cuda_runtime.h>

#define NB   4
#define SQL  2048
#define SKL  2048
#define DIM  512
#define RAD  128
#define NREL 257   // 2*RAD+1

#define BM 128
#define BN 128
#define BK 16
#define BMP 132    // padded row length (floats) for smem tiles

// scratch for Q_rel[b,q,r] = Q[b,q,:] . rel_embeds[r,:]
__device__ float g_qrel[(size_t)NB * SQL * NREL];

// ---------------------------------------------------------------------------
// GEMM 1: g_qrel[M, NREL] = Q[M, DIM] * RE[NREL, DIM]^T,  M = NB*SQL
// 64x64 tile, BK=16, 256 threads, 4x4 microtile (small, ~5% of runtime)
// ---------------------------------------------------------------------------
__global__ void __launch_bounds__(256) gemm_qrel_kernel(const float* __restrict__ Q,
                                                        const float* __restrict__ RE) {
    __shared__ float As[64][17];
    __shared__ float Bs[64][17];
    const int tid = threadIdx.x;
    const int tx = tid & 15, ty = tid >> 4;
    const int m0 = blockIdx.x * 64;
    const int n0 = blockIdx.y * 64;
    const int lr = tid >> 2;
    const int lk = (tid & 3) << 2;

    float acc[4][4] = {};

    for (int k0 = 0; k0 < DIM; k0 += 16) {
        float4 a4 = *(const float4*)(Q + (size_t)(m0 + lr) * DIM + k0 + lk);
        As[lr][lk + 0] = a4.x; As[lr][lk + 1] = a4.y;
        As[lr][lk + 2] = a4.z; As[lr][lk + 3] = a4.w;

        float4 b4 = make_float4(0.f, 0.f, 0.f, 0.f);
        if (n0 + lr < NREL)
            b4 = *(const float4*)(RE + (size_t)(n0 + lr) * DIM + k0 + lk);
        Bs[lr][lk + 0] = b4.x; Bs[lr][lk + 1] = b4.y;
        Bs[lr][lk + 2] = b4.z; Bs[lr][lk + 3] = b4.w;
        __syncthreads();

        #pragma unroll
        for (int kk = 0; kk < 16; kk++) {
            float a[4], b[4];
            #pragma unroll
            for (int i = 0; i < 4; i++) a[i] = As[ty * 4 + i][kk];
            #pragma unroll
            for (int j = 0; j < 4; j++) b[j] = Bs[tx * 4 + j][kk];
            #pragma unroll
            for (int i = 0; i < 4; i++)
                #pragma unroll
                for (int j = 0; j < 4; j++)
                    acc[i][j] = fmaf(a[i], b[j], acc[i][j]);
        }
        __syncthreads();
    }

    #pragma unroll
    for (int i = 0; i < 4; i++) {
        const int gm = m0 + ty * 4 + i;
        #pragma unroll
        for (int j = 0; j < 4; j++) {
            const int gn = n0 + tx * 4 + j;
            if (gn < NREL) g_qrel[(size_t)gm * NREL + gn] = acc[i][j];
        }
    }
}

// ---------------------------------------------------------------------------
// GEMM 2: scores[b,q,k] = (Q[b,q,:].K[b,k,:] + Q_rel[b,q,clip(k-q)+RAD]) / sqrt(DIM)
// 128x128x16 tile, 8x8 microtile, double-buffered smem, 256 threads.
// Both A (Q) and B (K) are K-major; tiles stored transposed: As[kk][m].
// ---------------------------------------------------------------------------
__global__ void __launch_bounds__(256, 2) gemm_scores_kernel(const float* __restrict__ Qg,
                                                             const float* __restrict__ Kg,
                                                             float* __restrict__ attn) {
    const int b = blockIdx.z;
    const float* A = Qg + (size_t)b * SQL * DIM;
    const float* B = Kg + (size_t)b * SKL * DIM;
    float* C = attn + (size_t)b * SQL * SKL;

    __shared__ float As[2][BK][BMP];
    __shared__ float Bs[2][BK][BMP];

    const int tid = threadIdx.x;
    const int tx = tid & 15;       // n dimension, 0..15
    const int ty = tid >> 4;       // m dimension, 0..15
    const int m0 = blockIdx.x * BM;
    const int n0 = blockIdx.y * BN;

    const int lr = tid >> 2;        // 0..63 (row within half-tile)
    const int lc = (tid & 3) << 2;  // k offset: 0,4,8,12

    float4 pa0, pa1, pb0, pb1;

    // prefetch tile 0
    pa0 = *(const float4*)(A + (size_t)(m0 + lr)      * DIM + lc);
    pa1 = *(const float4*)(A + (size_t)(m0 + lr + 64) * DIM + lc);
    pb0 = *(const float4*)(B + (size_t)(n0 + lr)      * DIM + lc);
    pb1 = *(const float4*)(B + (size_t)(n0 + lr + 64) * DIM + lc);

    As[0][lc + 0][lr] = pa0.x; As[0][lc + 1][lr] = pa0.y;
    As[0][lc + 2][lr] = pa0.z; As[0][lc + 3][lr] = pa0.w;
    As[0][lc + 0][lr + 64] = pa1.x; As[0][lc + 1][lr + 64] = pa1.y;
    As[0][lc + 2][lr + 64] = pa1.z; As[0][lc + 3][lr + 64] = pa1.w;
    Bs[0][lc + 0][lr] = pb0.x; Bs[0][lc + 1][lr] = pb0.y;
    Bs[0][lc + 2][lr] = pb0.z; Bs[0][lc + 3][lr] = pb0.w;
    Bs[0][lc + 0][lr + 64] = pb1.x; Bs[0][lc + 1][lr + 64] = pb1.y;
    Bs[0][lc + 2][lr + 64] = pb1.z; Bs[0][lc + 3][lr + 64] = pb1.w;
    __syncthreads();

    float acc[8][8] = {};
    int buf = 0;

    for (int k0 = 0; k0 < DIM; k0 += BK) {
        const int kn = k0 + BK;
        if (kn < DIM) {
            pa0 = *(const float4*)(A + (size_t)(m0 + lr)      * DIM + kn + lc);
            pa1 = *(const float4*)(A + (size_t)(m0 + lr + 64) * DIM + kn + lc);
            pb0 = *(const float4*)(B + (size_t)(n0 + lr)      * DIM + kn + lc);
            pb1 = *(const float4*)(B + (size_t)(n0 + lr + 64) * DIM + kn + lc);
        }

        #pragma unroll
        for (int kk = 0; kk < BK; kk++) {
            float4 av0 = *(const float4*)&As[buf][kk][ty * 8];
            float4 av1 = *(const float4*)&As[buf][kk][ty * 8 + 4];
            float4 bv0 = *(const float4*)&Bs[buf][kk][tx * 8];
            float4 bv1 = *(const float4*)&Bs[buf][kk][tx * 8 + 4];
            float a[8] = {av0.x, av0.y, av0.z, av0.w, av1.x, av1.y, av1.z, av1.w};
            float bb[8] = {bv0.x, bv0.y, bv0.z, bv0.w, bv1.x, bv1.y, bv1.z, bv1.w};
            #pragma unroll
            for (int i = 0; i < 8; i++)
                #pragma unroll
                for (int j = 0; j < 8; j++)
                    acc[i][j] = fmaf(a[i], bb[j], acc[i][j]);
        }

        if (kn < DIM) {
            const int nb = buf ^ 1;
            As[nb][lc + 0][lr] = pa0.x; As[nb][lc + 1][lr] = pa0.y;
            As[nb][lc + 2][lr] = pa0.z; As[nb][lc + 3][lr] = pa0.w;
            As[nb][lc + 0][lr + 64] = pa1.x; As[nb][lc + 1][lr + 64] = pa1.y;
            As[nb][lc + 2][lr + 64] = pa1.z; As[nb][lc + 3][lr + 64] = pa1.w;
            Bs[nb][lc + 0][lr] = pb0.x; Bs[nb][lc + 1][lr] = pb0.y;
            Bs[nb][lc + 2][lr] = pb0.z; Bs[nb][lc + 3][lr] = pb0.w;
            Bs[nb][lc + 0][lr + 64] = pb1.x; Bs[nb][lc + 1][lr + 64] = pb1.y;
            Bs[nb][lc + 2][lr + 64] = pb1.z; Bs[nb][lc + 3][lr + 64] = pb1.w;
            __syncthreads();
            buf = nb;
        }
    }

    const float inv_norm = 0.04419417382415922f;  // 1/sqrt(512)
    #pragma unroll
    for (int i = 0; i < 8; i++) {
        const int q = m0 + ty * 8 + i;
        const float* __restrict__ qr = &g_qrel[((size_t)b * SQL + q) * NREL];
        float out[8];
        #pragma unroll
        for (int j = 0; j < 8; j++) {
            const int kc = n0 + tx * 8 + j;
            int rel = kc - q;
            rel = max(-RAD, min(RAD, rel)) + RAD;
            out[j] = (acc[i][j] + qr[rel]) * inv_norm;
        }
        float* cp = C + (size_t)q * SKL + n0 + tx * 8;
        *(float4*)(cp)     = make_float4(out[0], out[1], out[2], out[3]);
        *(float4*)(cp + 4) = make_float4(out[4], out[5], out[6], out[7]);
    }
}

// ---------------------------------------------------------------------------
// Row softmax over SKL=2048 columns. One block (256 threads) per row.
// ---------------------------------------------------------------------------
__global__ void __launch_bounds__(256) softmax_rows_kernel(float* __restrict__ attn) {
    __shared__ float red[8];
    float* p = attn + (size_t)blockIdx.x * SKL;
    const int t = threadIdx.x;

    float v[8];
    float mx = -1e30f;
    #pragma unroll
    for (int i = 0; i < 8; i++) {
        v[i] = p[t + i * 256];
        mx = fmaxf(mx, v[i]);
    }
    #pragma unroll
    for (int o = 16; o > 0; o >>= 1) mx = fmaxf(mx, __shfl_xor_sync(0xffffffffu, mx, o));
    if ((t & 31) == 0) red[t >> 5] = mx;
    __syncthreads();
    float bmx = red[0];
    #pragma unroll
    for (int i = 1; i < 8; i++) bmx = fmaxf(bmx, red[i]);
    __syncthreads();

    float s = 0.f;
    #pragma unroll
    for (int i = 0; i < 8; i++) {
        v[i] = __expf(v[i] - bmx);
        s += v[i];
    }
    #pragma unroll
    for (int o = 16; o > 0; o >>= 1) s += __shfl_xor_sync(0xffffffffu, s, o);
    if ((t & 31) == 0) red[t >> 5] = s;
    __syncthreads();
    float tot = 0.f;
    #pragma unroll
    for (int i = 0; i < 8; i++) tot += red[i];
    const float inv = 1.0f / tot;

    #pragma unroll
    for (int i = 0; i < 8; i++) p[t + i * 256] = v[i] * inv;
}

// ---------------------------------------------------------------------------
// GEMM 3: Z[b,q,n] = sum_k attn[b,q,k] * V[b,k,n]  (NN GEMM, K = SKL = 2048)
// 128x128x16 tile, 8x8 microtile, double-buffered smem.
// A (attn) stored transposed As[kk][m]; B (V) stored direct Bs[kk][n].
// ---------------------------------------------------------------------------
__global__ void __launch_bounds__(256, 2) gemm_av_kernel(const float* __restrict__ attn,
                                                         const float* __restrict__ Vg,
                                                         float* __restrict__ Z) {
    const int b = blockIdx.z;
    const float* A = attn + (size_t)b * SQL * SKL;
    const float* B = Vg + (size_t)b * SKL * DIM;
    float* C = Z + (size_t)b * SQL * DIM;

    __shared__ float As[2][BK][BMP];
    __shared__ float Bs[2][BK][BMP];

    const int tid = threadIdx.x;
    const int tx = tid & 15;
    const int ty = tid >> 4;
    const int m0 = blockIdx.x * BM;
    const int n0 = blockIdx.y * BN;

    const int lr = tid >> 2;        // 0..63
    const int lc = (tid & 3) << 2;  // 0,4,8,12
    const int br = tid >> 5;        // 0..7  (B tile row)
    const int bc = (tid & 31) << 2; // 0..124 (B tile col, float4)

    float4 pa0, pa1, pb0, pb1;

    pa0 = *(const float4*)(A + (size_t)(m0 + lr)      * SKL + lc);
    pa1 = *(const float4*)(A + (size_t)(m0 + lr + 64) * SKL + lc);
    pb0 = *(const float4*)(B + (size_t)(br)     * DIM + n0 + bc);
    pb1 = *(const float4*)(B + (size_t)(br + 8) * DIM + n0 + bc);

    As[0][lc + 0][lr] = pa0.x; As[0][lc + 1][lr] = pa0.y;
    As[0][lc + 2][lr] = pa0.z; As[0][lc + 3][lr] = pa0.w;
    As[0][lc + 0][lr + 64] = pa1.x; As[0][lc + 1][lr + 64] = pa1.y;
    As[0][lc + 2][lr + 64] = pa1.z; As[0][lc + 3][lr + 64] = pa1.w;
    *(float4*)&Bs[0][br][bc]     = pb0;
    *(float4*)&Bs[0][br + 8][bc] = pb1;
    __syncthreads();

    float acc[8][8] = {};
    int buf = 0;

    for (int k0 = 0; k0 < SKL; k0 += BK) {
        const int kn = k0 + BK;
        if (kn < SKL) {
            pa0 = *(const float4*)(A + (size_t)(m0 + lr)      * SKL + kn + lc);
            pa1 = *(const float4*)(A + (size_t)(m0 + lr + 64) * SKL + kn + lc);
            pb0 = *(const float4*)(B + (size_t)(kn + br)     * DIM + n0 + bc);
            pb1 = *(const float4*)(B + (size_t)(kn + br + 8) * DIM + n0 + bc);
        }

        #pragma unroll
        for (int kk = 0; kk < BK; kk++) {
            float4 av0 = *(const float4*)&As[buf][kk][ty * 8];
            float4 av1 = *(const float4*)&As[buf][kk][ty * 8 + 4];
            float4 bv0 = *(const float4*)&Bs[buf][kk][tx * 8];
            float4 bv1 = *(const float4*)&Bs[buf][kk][tx * 8 + 4];
            float a[8] = {av0.x, av0.y, av0.z, av0.w, av1.x, av1.y, av1.z, av1.w};
            float bb[8] = {bv0.x, bv0.y, bv0.z, bv0.w, bv1.x, bv1.y, bv1.z, bv1.w};
            #pragma unroll
            for (int i = 0; i < 8; i++)
                #pragma unroll
                for (int j = 0; j < 8; j++)
                    acc[i][j] = fmaf(a[i], bb[j], acc[i][j]);
        }

        if (kn < SKL) {
            const int nb = buf ^ 1;
            As[nb][lc + 0][lr] = pa0.x; As[nb][lc + 1][lr] = pa0.y;
            As[nb][lc + 2][lr] = pa0.z; As[nb][lc + 3][lr] = pa0.w;
            As[nb][lc + 0][lr + 64] = pa1.x; As[nb][lc + 1][lr + 64] = pa1.y;
            As[nb][lc + 2][lr + 64] = pa1.z; As[nb][lc + 3][lr + 64] = pa1.w;
            *(float4*)&Bs[nb][br][bc]     = pb0;
            *(float4*)&Bs[nb][br + 8][bc] = pb1;
            __syncthreads();
            buf = nb;
        }
    }

    #pragma unroll
    for (int i = 0; i < 8; i++) {
        const int gm = m0 + ty * 8 + i;
        float* cp = C + (size_t)gm * DIM + n0 + tx * 8;
        *(float4*)(cp)     = make_float4(acc[i][0], acc[i][1], acc[i][2], acc[i][3]);
        *(float4*)(cp + 4) = make_float4(acc[i][4], acc[i][5], acc[i][6], acc[i][7]);
    }
}

// ---------------------------------------------------------------------------
extern "C" void kernel_launch(void* const* d_in, const int* in_sizes, int n_in,
                              void* d_out, int out_size) {
    const float* Q  = (const float*)d_in[0];
    const float* K  = (const float*)d_in[1];
    const float* V  = (const float*)d_in[2];
    const float* RE = (const float*)d_in[3];

    float* attn = (float*)d_out;                                   // [NB, SQL, SKL]
    float* Z    = attn + (size_t)NB * SQL * SKL;                   // [NB, SQL, DIM]

    // 1) Q_rel = Q @ rel_embeds^T -> g_qrel
    {
        dim3 grid((NB * SQL) / 64, (NREL + 63) / 64);
        gemm_qrel_kernel<<<grid, 256>>>(Q, RE);
    }
    // 2) scores = (Q@K^T + rel_shift) / sqrt(d) -> attn region (raw)
    {
        dim3 grid(SQL / BM, SKL / BN, NB);
        gemm_scores_kernel<<<grid, 256>>>(Q, K, attn);
    }
    // 3) softmax rows in place
    {
        softmax_rows_kernel<<<NB * SQL, 256>>>(attn);
    }
    // 4) Z = attn @ V
    {
        dim3 grid(SQL / BM, DIM / BN, NB);
        gemm_av_kernel<<<grid, 256>>>(attn, V, Z);
    }
}

// round 3
// speedup vs baseline: 2.2713x; 1.8062x over previous
#include <cuda_runtime.h>
#include <cuda_bf16.h>
#include <cstdint>

using bf16 = __nv_bfloat16;

#define NB   4
#define SQL  2048
#define SKL  2048
#define DIM  512
#define RAD  128
#define NREL 257

// ---------------- device scratch ----------------
__device__ float g_qrel[(size_t)NB * SQL * NREL];
__device__ bf16 g_Qh[(size_t)NB * SQL * DIM];
__device__ bf16 g_Ql[(size_t)NB * SQL * DIM];
__device__ bf16 g_Kh[(size_t)NB * SKL * DIM];
__device__ bf16 g_Kl[(size_t)NB * SKL * DIM];
__device__ bf16 g_Vth[(size_t)NB * DIM * SKL];   // V transposed: [b][n][k]
__device__ bf16 g_Vtl[(size_t)NB * DIM * SKL];
__device__ bf16 g_Ah[(size_t)NB * SQL * SKL];    // attn split
__device__ bf16 g_Al[(size_t)NB * SQL * SKL];

// ---------------- helpers ----------------
__device__ __forceinline__ uint32_t smem_u32(const void* p) {
    return (uint32_t)__cvta_generic_to_shared(p);
}

#define CP16(saddr, gptr) \
    asm volatile("cp.async.cg.shared.global [%0], [%1], 16;" :: "r"(saddr), "l"(gptr))
#define CP_COMMIT() asm volatile("cp.async.commit_group;")
#define CP_WAIT0()  asm volatile("cp.async.wait_group 0;" ::: "memory")

#define MMA_BF16(d, a0, a1, a2, a3, b0, b1)                                       \
    asm volatile(                                                                 \
        "mma.sync.aligned.m16n8k16.row.col.f32.bf16.bf16.f32 "                    \
        "{%0,%1,%2,%3},{%4,%5,%6,%7},{%8,%9},{%0,%1,%2,%3};"                      \
        : "+f"((d)[0]), "+f"((d)[1]), "+f"((d)[2]), "+f"((d)[3])                  \
        : "r"(a0), "r"(a1), "r"(a2), "r"(a3), "r"(b0), "r"(b1))

__device__ __forceinline__ uint32_t lds32(const bf16* s, int off) {
    return *(const uint32_t*)(s + off);
}

// ---------------------------------------------------------------------------
// split fp32 -> (bf16 hi, bf16 lo)
// ---------------------------------------------------------------------------
__global__ void __launch_bounds__(256) split_hl_kernel(const float* __restrict__ x,
                                                       bf16* __restrict__ hi,
                                                       bf16* __restrict__ lo) {
    const size_t i = ((size_t)blockIdx.x * 256 + threadIdx.x) * 4;
    float4 v = *(const float4*)(x + i);
    bf16 h0 = __float2bfloat16(v.x), h1 = __float2bfloat16(v.y);
    bf16 h2 = __float2bfloat16(v.z), h3 = __float2bfloat16(v.w);
    bf16 l0 = __float2bfloat16(v.x - __bfloat162float(h0));
    bf16 l1 = __float2bfloat16(v.y - __bfloat162float(h1));
    bf16 l2 = __float2bfloat16(v.z - __bfloat162float(h2));
    bf16 l3 = __float2bfloat16(v.w - __bfloat162float(h3));
    __nv_bfloat162* ph = (__nv_bfloat162*)(hi + i);
    __nv_bfloat162* pl = (__nv_bfloat162*)(lo + i);
    ph[0] = __nv_bfloat162{h0, h1}; ph[1] = __nv_bfloat162{h2, h3};
    pl[0] = __nv_bfloat162{l0, l1}; pl[1] = __nv_bfloat162{l2, l3};
}

// ---------------------------------------------------------------------------
// V [b][k][n] -> Vt hi/lo [b][n][k]
// ---------------------------------------------------------------------------
__global__ void __launch_bounds__(256) split_v_t_kernel(const float* __restrict__ V,
                                                        bf16* __restrict__ Vth,
                                                        bf16* __restrict__ Vtl) {
    __shared__ float t[32][33];
    const int b = blockIdx.z;
    const int k0 = blockIdx.x * 32;
    const int n0 = blockIdx.y * 32;
    const int tx = threadIdx.x;       // 0..31
    const int ty = threadIdx.y;       // 0..7
    const float* Vb = V + (size_t)b * SKL * DIM;

    #pragma unroll
    for (int i = 0; i < 4; i++)
        t[ty + i * 8][tx] = Vb[(size_t)(k0 + ty + i * 8) * DIM + n0 + tx];
    __syncthreads();

    #pragma unroll
    for (int i = 0; i < 4; i++) {
        float v = t[tx][ty + i * 8];
        bf16 h = __float2bfloat16(v);
        bf16 l = __float2bfloat16(v - __bfloat162float(h));
        size_t idx = (size_t)b * DIM * SKL + (size_t)(n0 + ty + i * 8) * SKL + k0 + tx;
        Vth[idx] = h;
        Vtl[idx] = l;
    }
}

// ---------------------------------------------------------------------------
// GEMM 1 (small, fp32): g_qrel = Q @ rel_embeds^T
// ---------------------------------------------------------------------------
__global__ void __launch_bounds__(256) gemm_qrel_kernel(const float* __restrict__ Q,
                                                        const float* __restrict__ RE) {
    __shared__ float As[64][17];
    __shared__ float Bs[64][17];
    const int tid = threadIdx.x;
    const int tx = tid & 15, ty = tid >> 4;
    const int m0 = blockIdx.x * 64;
    const int n0 = blockIdx.y * 64;
    const int lr = tid >> 2;
    const int lk = (tid & 3) << 2;

    float acc[4][4] = {};

    for (int k0 = 0; k0 < DIM; k0 += 16) {
        float4 a4 = *(const float4*)(Q + (size_t)(m0 + lr) * DIM + k0 + lk);
        As[lr][lk + 0] = a4.x; As[lr][lk + 1] = a4.y;
        As[lr][lk + 2] = a4.z; As[lr][lk + 3] = a4.w;
        float4 b4 = make_float4(0.f, 0.f, 0.f, 0.f);
        if (n0 + lr < NREL)
            b4 = *(const float4*)(RE + (size_t)(n0 + lr) * DIM + k0 + lk);
        Bs[lr][lk + 0] = b4.x; Bs[lr][lk + 1] = b4.y;
        Bs[lr][lk + 2] = b4.z; Bs[lr][lk + 3] = b4.w;
        __syncthreads();
        #pragma unroll
        for (int kk = 0; kk < 16; kk++) {
            float a[4], b[4];
            #pragma unroll
            for (int i = 0; i < 4; i++) a[i] = As[ty * 4 + i][kk];
            #pragma unroll
            for (int j = 0; j < 4; j++) b[j] = Bs[tx * 4 + j][kk];
            #pragma unroll
            for (int i = 0; i < 4; i++)
                #pragma unroll
                for (int j = 0; j < 4; j++)
                    acc[i][j] = fmaf(a[i], b[j], acc[i][j]);
        }
        __syncthreads();
    }
    #pragma unroll
    for (int i = 0; i < 4; i++) {
        const int gm = m0 + ty * 4 + i;
        #pragma unroll
        for (int j = 0; j < 4; j++) {
            const int gn = n0 + tx * 4 + j;
            if (gn < NREL) g_qrel[(size_t)gm * NREL + gn] = acc[i][j];
        }
    }
}

// ---------------------------------------------------------------------------
// Tensor-core GEMM (bf16 hi/lo x3): C[m][n] = sum_k A[m,k]*B[n,k]
// 128x128x32 tile, 8 warps, warp tile 64x32, cp.async double buffer.
// SCORES: epilogue adds rel-pos + scale. else: plain store.
// ---------------------------------------------------------------------------
template<int KDIM, bool SCORES>
__global__ void __launch_bounds__(256, 2) mma_gemm_kernel(
    const bf16* __restrict__ Ah, const bf16* __restrict__ Al,
    const bf16* __restrict__ Bh, const bf16* __restrict__ Bl,
    float* __restrict__ C, int bRows, int ldc)
{
    extern __shared__ __align__(16) bf16 sm[];
    bf16* sAh = sm;                 // [2][128][40]
    bf16* sAl = sm + 10240;
    bf16* sBh = sm + 20480;
    bf16* sBl = sm + 30720;

    const int tid = threadIdx.x;
    const int lane = tid & 31;
    const int wid = tid >> 5;
    const int wm = (wid >> 2) * 64;
    const int wn = (wid & 3) * 32;
    const int l4 = lane >> 2;
    const int q2 = (lane & 3) * 2;

    const int b = blockIdx.z;
    const int m0 = blockIdx.x * 128;
    const int n0 = blockIdx.y * 128;

    const bf16* gAh = Ah + (size_t)b * SQL * KDIM;
    const bf16* gAl = Al + (size_t)b * SQL * KDIM;
    const bf16* gBh = Bh + (size_t)b * bRows * KDIM;
    const bf16* gBl = Bl + (size_t)b * bRows * KDIM;

    const int lr = tid >> 2;            // 0..63 base; combined with p gives 0..127
    // loader: idx = tid + p*256; r = idx>>2 (0..127); c = (idx&3)*8

    auto load_stage = [&](int buf, int k0) {
        #pragma unroll
        for (int p = 0; p < 2; p++) {
            int idx = tid + p * 256;
            int r = idx >> 2;
            int c = (idx & 3) << 3;
            size_t ga = (size_t)(m0 + r) * KDIM + k0 + c;
            size_t gb = (size_t)(n0 + r) * KDIM + k0 + c;
            int so = buf * 5120 + r * 40 + c;
            CP16(smem_u32(sAh + so), gAh + ga);
            CP16(smem_u32(sAl + so), gAl + ga);
            CP16(smem_u32(sBh + so), gBh + gb);
            CP16(smem_u32(sBl + so), gBl + gb);
        }
        CP_COMMIT();
    };
    (void)lr;

    float acc[4][4][4] = {};

    load_stage(0, 0);
    CP_WAIT0();
    __syncthreads();

    int buf = 0;
    for (int k0 = 0; k0 < KDIM; k0 += 32) {
        const bool has_next = (k0 + 32) < KDIM;
        if (has_next) load_stage(buf ^ 1, k0 + 32);

        #pragma unroll
        for (int kk = 0; kk < 32; kk += 16) {
            uint32_t ah[4][4], al[4][4];
            const int abase = buf * 5120 + kk + q2;
            #pragma unroll
            for (int mf = 0; mf < 4; mf++) {
                const int r0 = (wm + mf * 16 + l4) * 40;
                ah[mf][0] = lds32(sAh, abase + r0);
                ah[mf][1] = lds32(sAh, abase + r0 + 8 * 40);
                ah[mf][2] = lds32(sAh, abase + r0 + 8);
                ah[mf][3] = lds32(sAh, abase + r0 + 8 * 40 + 8);
                al[mf][0] = lds32(sAl, abase + r0);
                al[mf][1] = lds32(sAl, abase + r0 + 8 * 40);
                al[mf][2] = lds32(sAl, abase + r0 + 8);
                al[mf][3] = lds32(sAl, abase + r0 + 8 * 40 + 8);
            }
            #pragma unroll
            for (int nf = 0; nf < 4; nf++) {
                const int rb = (wn + nf * 8 + l4) * 40;
                uint32_t bh0 = lds32(sBh, abase + rb);
                uint32_t bh1 = lds32(sBh, abase + rb + 8);
                uint32_t bl0 = lds32(sBl, abase + rb);
                uint32_t bl1 = lds32(sBl, abase + rb + 8);
                #pragma unroll
                for (int mf = 0; mf < 4; mf++) {
                    MMA_BF16(acc[mf][nf], ah[mf][0], ah[mf][1], ah[mf][2], ah[mf][3], bh0, bh1);
                    MMA_BF16(acc[mf][nf], ah[mf][0], ah[mf][1], ah[mf][2], ah[mf][3], bl0, bl1);
                    MMA_BF16(acc[mf][nf], al[mf][0], al[mf][1], al[mf][2], al[mf][3], bh0, bh1);
                }
            }
        }

        if (has_next) CP_WAIT0();
        __syncthreads();
        buf ^= 1;
    }

    float* Cb = C + (size_t)b * SQL * ldc;
    const float inv_norm = 0.04419417382415922f;   // 1/sqrt(512)

    #pragma unroll
    for (int mf = 0; mf < 4; mf++) {
        const int q0 = m0 + wm + mf * 16 + l4;
        const int q1 = q0 + 8;
        #pragma unroll
        for (int nf = 0; nf < 4; nf++) {
            const int col = n0 + wn + nf * 8 + q2;
            float* d = acc[mf][nf];
            if (SCORES) {
                const float* qr0 = g_qrel + ((size_t)b * SQL + q0) * NREL;
                const float* qr1 = qr0 + (size_t)8 * NREL;
                int r00 = min(RAD, max(-RAD, col - q0)) + RAD;
                int r01 = min(RAD, max(-RAD, col + 1 - q0)) + RAD;
                int r10 = min(RAD, max(-RAD, col - q1)) + RAD;
                int r11 = min(RAD, max(-RAD, col + 1 - q1)) + RAD;
                float2 o0 = make_float2((d[0] + qr0[r00]) * inv_norm,
                                        (d[1] + qr0[r01]) * inv_norm);
                float2 o1 = make_float2((d[2] + qr1[r10]) * inv_norm,
                                        (d[3] + qr1[r11]) * inv_norm);
                *(float2*)(Cb + (size_t)q0 * ldc + col) = o0;
                *(float2*)(Cb + (size_t)q1 * ldc + col) = o1;
            } else {
                *(float2*)(Cb + (size_t)q0 * ldc + col) = make_float2(d[0], d[1]);
                *(float2*)(Cb + (size_t)q1 * ldc + col) = make_float2(d[2], d[3]);
            }
        }
    }
}

// ---------------------------------------------------------------------------
// Row softmax (in place, fp32) + write bf16 hi/lo split of attn
// ---------------------------------------------------------------------------
__global__ void __launch_bounds__(256) softmax_split_kernel(float* __restrict__ attn) {
    __shared__ float red[8];
    float* p = attn + (size_t)blockIdx.x * SKL;
    const size_t gbase = (size_t)blockIdx.x * SKL;
    const int t = threadIdx.x;

    float v[8];
    float mx = -1e30f;
    #pragma unroll
    for (int i = 0; i < 8; i++) {
        v[i] = p[t + i * 256];
        mx = fmaxf(mx, v[i]);
    }
    #pragma unroll
    for (int o = 16; o > 0; o >>= 1) mx = fmaxf(mx, __shfl_xor_sync(0xffffffffu, mx, o));
    if ((t & 31) == 0) red[t >> 5] = mx;
    __syncthreads();
    float bmx = red[0];
    #pragma unroll
    for (int i = 1; i < 8; i++) bmx = fmaxf(bmx, red[i]);
    __syncthreads();

    float s = 0.f;
    #pragma unroll
    for (int i = 0; i < 8; i++) {
        v[i] = __expf(v[i] - bmx);
        s += v[i];
    }
    #pragma unroll
    for (int o = 16; o > 0; o >>= 1) s += __shfl_xor_sync(0xffffffffu, s, o);
    if ((t & 31) == 0) red[t >> 5] = s;
    __syncthreads();
    float tot = 0.f;
    #pragma unroll
    for (int i = 0; i < 8; i++) tot += red[i];
    const float inv = 1.0f / tot;

    #pragma unroll
    for (int i = 0; i < 8; i++) {
        float val = v[i] * inv;
        p[t + i * 256] = val;
        bf16 h = __float2bfloat16(val);
        bf16 l = __float2bfloat16(val - __bfloat162float(h));
        g_Ah[gbase + t + i * 256] = h;
        g_Al[gbase + t + i * 256] = l;
    }
}

// ---------------------------------------------------------------------------
extern "C" void kernel_launch(void* const* d_in, const int* in_sizes, int n_in,
                              void* d_out, int out_size) {
    const float* Q  = (const float*)d_in[0];
    const float* K  = (const float*)d_in[1];
    const float* V  = (const float*)d_in[2];
    const float* RE = (const float*)d_in[3];

    float* attn = (float*)d_out;
    float* Z    = attn + (size_t)NB * SQL * SKL;

    bf16 *Qh, *Ql, *Kh, *Kl, *Vth, *Vtl, *Ahp, *Alp;
    cudaGetSymbolAddress((void**)&Qh,  g_Qh);
    cudaGetSymbolAddress((void**)&Ql,  g_Ql);
    cudaGetSymbolAddress((void**)&Kh,  g_Kh);
    cudaGetSymbolAddress((void**)&Kl,  g_Kl);
    cudaGetSymbolAddress((void**)&Vth, g_Vth);
    cudaGetSymbolAddress((void**)&Vtl, g_Vtl);
    cudaGetSymbolAddress((void**)&Ahp, g_Ah);
    cudaGetSymbolAddress((void**)&Alp, g_Al);

    const int SMEM_GEMM = 81920;
    cudaFuncSetAttribute(mma_gemm_kernel<DIM, true>,
                         cudaFuncAttributeMaxDynamicSharedMemorySize, SMEM_GEMM);
    cudaFuncSetAttribute(mma_gemm_kernel<SKL, false>,
                         cudaFuncAttributeMaxDynamicSharedMemorySize, SMEM_GEMM);

    // splits
    split_hl_kernel<<<(NB * SQL * DIM) / 1024, 256>>>(Q, Qh, Ql);
    split_hl_kernel<<<(NB * SKL * DIM) / 1024, 256>>>(K, Kh, Kl);
    {
        dim3 grid(SKL / 32, DIM / 32, NB);
        split_v_t_kernel<<<grid, dim3(32, 8)>>>(V, Vth, Vtl);
    }
    // Q_rel
    {
        dim3 grid((NB * SQL) / 64, (NREL + 63) / 64);
        gemm_qrel_kernel<<<grid, 256>>>(Q, RE);
    }
    // scores (raw energies into attn region)
    {
        dim3 grid(SQL / 128, SKL / 128, NB);
        mma_gemm_kernel<DIM, true><<<grid, 256, SMEM_GEMM>>>(Qh, Ql, Kh, Kl,
                                                             attn, SKL, SKL);
    }
    // softmax + split
    softmax_split_kernel<<<NB * SQL, 256>>>(attn);
    // Z = attn @ V
    {
        dim3 grid(SQL / 128, DIM / 128, NB);
        mma_gemm_kernel<SKL, false><<<grid, 256, SMEM_GEMM>>>(Ahp, Alp, Vth, Vtl,
                                                              Z, DIM, DIM);
    }
}

// round 5
// speedup vs baseline: 2.6267x; 1.1565x over previous
#include <cuda_runtime.h>
#include <cuda_bf16.h>
#include <cstdint>

using bf16 = __nv_bfloat16;

#define NB   4
#define SQL  2048
#define SKL  2048
#define DIM  512
#define RAD  128
#define NREL 257
#define NRELP 384   // padded

// ---------------- device scratch ----------------
__device__ float g_qrel[(size_t)NB * SQL * NRELP];
__device__ bf16 g_Qh[(size_t)NB * SQL * DIM];
__device__ bf16 g_Ql[(size_t)NB * SQL * DIM];
__device__ bf16 g_Kh[(size_t)NB * SKL * DIM];
__device__ bf16 g_Kl[(size_t)NB * SKL * DIM];
__device__ bf16 g_REh[(size_t)NRELP * DIM];
__device__ bf16 g_REl[(size_t)NRELP * DIM];
__device__ bf16 g_Vth[(size_t)NB * DIM * SKL];   // V transposed: [b][n][k]
__device__ bf16 g_Vtl[(size_t)NB * DIM * SKL];
__device__ bf16 g_Ah[(size_t)NB * SQL * SKL];    // attn split
__device__ bf16 g_Al[(size_t)NB * SQL * SKL];

// ---------------- helpers ----------------
__device__ __forceinline__ uint32_t smem_u32(const void* p) {
    return (uint32_t)__cvta_generic_to_shared(p);
}

#define CP16(saddr, gptr) \
    asm volatile("cp.async.cg.shared.global [%0], [%1], 16;" :: "r"(saddr), "l"(gptr))
#define CP_COMMIT() asm volatile("cp.async.commit_group;")
#define CP_WAIT0()  asm volatile("cp.async.wait_group 0;" ::: "memory")

#define MMA_BF16(d, a0, a1, a2, a3, b0, b1)                                       \
    asm volatile(                                                                 \
        "mma.sync.aligned.m16n8k16.row.col.f32.bf16.bf16.f32 "                    \
        "{%0,%1,%2,%3},{%4,%5,%6,%7},{%8,%9},{%0,%1,%2,%3};"                      \
        : "+f"((d)[0]), "+f"((d)[1]), "+f"((d)[2]), "+f"((d)[3])                  \
        : "r"(a0), "r"(a1), "r"(a2), "r"(a3), "r"(b0), "r"(b1))

#define LDSM_X4(r0, r1, r2, r3, addr)                                             \
    asm volatile("ldmatrix.sync.aligned.m8n8.x4.shared.b16 {%0,%1,%2,%3},[%4];"   \
        : "=r"(r0), "=r"(r1), "=r"(r2), "=r"(r3) : "r"(addr))

#define LDSM_X2(r0, r1, addr)                                                     \
    asm volatile("ldmatrix.sync.aligned.m8n8.x2.shared.b16 {%0,%1},[%2];"         \
        : "=r"(r0), "=r"(r1) : "r"(addr))

// ---------------------------------------------------------------------------
// split fp32 -> (bf16 hi, bf16 lo)
// ---------------------------------------------------------------------------
__global__ void __launch_bounds__(256) split_hl_kernel(const float* __restrict__ x,
                                                       bf16* __restrict__ hi,
                                                       bf16* __restrict__ lo) {
    const size_t i = ((size_t)blockIdx.x * 256 + threadIdx.x) * 4;
    float4 v = *(const float4*)(x + i);
    bf16 h0 = __float2bfloat16(v.x), h1 = __float2bfloat16(v.y);
    bf16 h2 = __float2bfloat16(v.z), h3 = __float2bfloat16(v.w);
    bf16 l0 = __float2bfloat16(v.x - __bfloat162float(h0));
    bf16 l1 = __float2bfloat16(v.y - __bfloat162float(h1));
    bf16 l2 = __float2bfloat16(v.z - __bfloat162float(h2));
    bf16 l3 = __float2bfloat16(v.w - __bfloat162float(h3));
    __nv_bfloat162* ph = (__nv_bfloat162*)(hi + i);
    __nv_bfloat162* pl = (__nv_bfloat162*)(lo + i);
    ph[0] = __nv_bfloat162{h0, h1}; ph[1] = __nv_bfloat162{h2, h3};
    pl[0] = __nv_bfloat162{l0, l1}; pl[1] = __nv_bfloat162{l2, l3};
}

// RE [257,512] -> padded [384,512] hi/lo (rows >=257 zero)
__global__ void __launch_bounds__(128) split_re_kernel(const float* __restrict__ RE,
                                                       bf16* __restrict__ REh,
                                                       bf16* __restrict__ REl) {
    const int row = blockIdx.x;
    const int c = threadIdx.x * 4;
    bf16 h[4] = {}, l[4] = {};
    if (row < NREL) {
        float4 v = *(const float4*)(RE + (size_t)row * DIM + c);
        h[0] = __float2bfloat16(v.x); l[0] = __float2bfloat16(v.x - __bfloat162float(h[0]));
        h[1] = __float2bfloat16(v.y); l[1] = __float2bfloat16(v.y - __bfloat162float(h[1]));
        h[2] = __float2bfloat16(v.z); l[2] = __float2bfloat16(v.z - __bfloat162float(h[2]));
        h[3] = __float2bfloat16(v.w); l[3] = __float2bfloat16(v.w - __bfloat162float(h[3]));
    }
    *(float2*)(REh + (size_t)row * DIM + c) = *(float2*)h;
    *(float2*)(REl + (size_t)row * DIM + c) = *(float2*)l;
}

// ---------------------------------------------------------------------------
// V [b][k][n] -> Vt hi/lo [b][n][k]
// ---------------------------------------------------------------------------
__global__ void __launch_bounds__(256) split_v_t_kernel(const float* __restrict__ V,
                                                        bf16* __restrict__ Vth,
                                                        bf16* __restrict__ Vtl) {
    __shared__ float t[32][33];
    const int b = blockIdx.z;
    const int k0 = blockIdx.x * 32;
    const int n0 = blockIdx.y * 32;
    const int tx = threadIdx.x;
    const int ty = threadIdx.y;
    const float* Vb = V + (size_t)b * SKL * DIM;

    #pragma unroll
    for (int i = 0; i < 4; i++)
        t[ty + i * 8][tx] = Vb[(size_t)(k0 + ty + i * 8) * DIM + n0 + tx];
    __syncthreads();

    #pragma unroll
    for (int i = 0; i < 4; i++) {
        float v = t[tx][ty + i * 8];
        bf16 h = __float2bfloat16(v);
        bf16 l = __float2bfloat16(v - __bfloat162float(h));
        size_t idx = (size_t)b * DIM * SKL + (size_t)(n0 + ty + i * 8) * SKL + k0 + tx;
        Vth[idx] = h;
        Vtl[idx] = l;
    }
}

// ---------------------------------------------------------------------------
// Tensor-core GEMM (bf16 hi/lo, 3 MMA terms): C[m][n] = sum_k A[m,k]*B[n,k]
// 128x128x32 tile, 8 warps (warp 64x32), cp.async double buffer, ldmatrix.
// ---------------------------------------------------------------------------
template<int KDIM, bool SCORES>
__global__ void __launch_bounds__(256, 2) mma_gemm_kernel(
    const bf16* __restrict__ Ah, const bf16* __restrict__ Al,
    const bf16* __restrict__ Bh, const bf16* __restrict__ Bl,
    float* __restrict__ C,
    size_t aBatch, size_t bBatch, size_t cBatch, int ldc)
{
    extern __shared__ __align__(16) bf16 sm[];
    bf16* sAh = sm;                 // [2][128][40]
    bf16* sAl = sm + 10240;
    bf16* sBh = sm + 20480;
    bf16* sBl = sm + 30720;

    const int tid = threadIdx.x;
    const int lane = tid & 31;
    const int wid = tid >> 5;
    const int wm = (wid >> 2) * 64;
    const int wn = (wid & 3) * 32;
    const int l4 = lane >> 2;
    const int q2 = (lane & 3) * 2;

    const int b = blockIdx.z;
    const int m0 = blockIdx.x * 128;
    const int n0 = blockIdx.y * 128;

    const bf16* gAh = Ah + (size_t)b * aBatch;
    const bf16* gAl = Al + (size_t)b * aBatch;
    const bf16* gBh = Bh + (size_t)b * bBatch;
    const bf16* gBl = Bl + (size_t)b * bBatch;

    auto load_stage = [&](int buf, int k0) {
        #pragma unroll
        for (int p = 0; p < 2; p++) {
            int idx = tid + p * 256;
            int r = idx >> 2;
            int c = (idx & 3) << 3;
            size_t ga = (size_t)(m0 + r) * KDIM + k0 + c;
            size_t gb = (size_t)(n0 + r) * KDIM + k0 + c;
            int so = buf * 5120 + r * 40 + c;
            CP16(smem_u32(sAh + so), gAh + ga);
            CP16(smem_u32(sAl + so), gAl + ga);
            CP16(smem_u32(sBh + so), gBh + gb);
            CP16(smem_u32(sBl + so), gBl + gb);
        }
        CP_COMMIT();
    };

    // ldmatrix per-thread base byte offsets (within a buffer, excluding kk)
    uint32_t aoff[4], boff[4];
    {
        const int ra = (lane & 15);
        const int ca = (lane >> 4) << 3;
        #pragma unroll
        for (int mf = 0; mf < 4; mf++)
            aoff[mf] = (uint32_t)(((wm + mf * 16 + ra) * 40 + ca) * 2);
        const int rb = (lane & 7);
        const int cb = ((lane >> 3) & 1) << 3;
        #pragma unroll
        for (int nf = 0; nf < 4; nf++)
            boff[nf] = (uint32_t)(((wn + nf * 8 + rb) * 40 + cb) * 2);
    }
    const uint32_t uAh = smem_u32(sAh), uAl = smem_u32(sAl);
    const uint32_t uBh = smem_u32(sBh), uBl = smem_u32(sBl);

    float acc[4][4][4] = {};

    load_stage(0, 0);
    CP_WAIT0();
    __syncthreads();

    int buf = 0;
    for (int k0 = 0; k0 < KDIM; k0 += 32) {
        const bool has_next = (k0 + 32) < KDIM;
        if (has_next) load_stage(buf ^ 1, k0 + 32);

        #pragma unroll
        for (int kk = 0; kk < 32; kk += 16) {
            const uint32_t kb = (uint32_t)(buf * 10240 + kk * 2);
            uint32_t ah[4][4], al[4][4];
            #pragma unroll
            for (int mf = 0; mf < 4; mf++) {
                LDSM_X4(ah[mf][0], ah[mf][1], ah[mf][2], ah[mf][3], uAh + kb + aoff[mf]);
                LDSM_X4(al[mf][0], al[mf][1], al[mf][2], al[mf][3], uAl + kb + aoff[mf]);
            }
            #pragma unroll
            for (int nf = 0; nf < 4; nf++) {
                uint32_t bh0, bh1, bl0, bl1;
                LDSM_X2(bh0, bh1, uBh + kb + boff[nf]);
                LDSM_X2(bl0, bl1, uBl + kb + boff[nf]);
                #pragma unroll
                for (int mf = 0; mf < 4; mf++) {
                    MMA_BF16(acc[mf][nf], ah[mf][0], ah[mf][1], ah[mf][2], ah[mf][3], bh0, bh1);
                    MMA_BF16(acc[mf][nf], ah[mf][0], ah[mf][1], ah[mf][2], ah[mf][3], bl0, bl1);
                    MMA_BF16(acc[mf][nf], al[mf][0], al[mf][1], al[mf][2], al[mf][3], bh0, bh1);
                }
            }
        }

        if (has_next) CP_WAIT0();
        __syncthreads();
        buf ^= 1;
    }

    float* Cb = C + (size_t)b * cBatch;
    const float inv_norm = 0.04419417382415922f;   // 1/sqrt(512)

    #pragma unroll
    for (int mf = 0; mf < 4; mf++) {
        const int q0 = m0 + wm + mf * 16 + l4;
        const int q1 = q0 + 8;
        #pragma unroll
        for (int nf = 0; nf < 4; nf++) {
            const int col = n0 + wn + nf * 8 + q2;
            float* d = acc[mf][nf];
            if (SCORES) {
                const float* qr0 = g_qrel + ((size_t)b * SQL + q0) * NRELP;
                const float* qr1 = qr0 + (size_t)8 * NRELP;
                int r00 = min(RAD, max(-RAD, col - q0)) + RAD;
                int r01 = min(RAD, max(-RAD, col + 1 - q0)) + RAD;
                int r10 = min(RAD, max(-RAD, col - q1)) + RAD;
                int r11 = min(RAD, max(-RAD, col + 1 - q1)) + RAD;
                float2 o0 = make_float2((d[0] + qr0[r00]) * inv_norm,
                                        (d[1] + qr0[r01]) * inv_norm);
                float2 o1 = make_float2((d[2] + qr1[r10]) * inv_norm,
                                        (d[3] + qr1[r11]) * inv_norm);
                *(float2*)(Cb + (size_t)q0 * ldc + col) = o0;
                *(float2*)(Cb + (size_t)q1 * ldc + col) = o1;
            } else {
                *(float2*)(Cb + (size_t)q0 * ldc + col) = make_float2(d[0], d[1]);
                *(float2*)(Cb + (size_t)q1 * ldc + col) = make_float2(d[2], d[3]);
            }
        }
    }
}

// ---------------------------------------------------------------------------
// Row softmax (in place, fp32) + write bf16 hi/lo split of attn
// ---------------------------------------------------------------------------
__global__ void __launch_bounds__(256) softmax_split_kernel(float* __restrict__ attn) {
    __shared__ float red[8];
    float* p = attn + (size_t)blockIdx.x * SKL;
    const size_t gbase = (size_t)blockIdx.x * SKL;
    const int t = threadIdx.x;

    float v[8];
    float mx = -1e30f;
    #pragma unroll
    for (int i = 0; i < 8; i++) {
        v[i] = p[t + i * 256];
        mx = fmaxf(mx, v[i]);
    }
    #pragma unroll
    for (int o = 16; o > 0; o >>= 1) mx = fmaxf(mx, __shfl_xor_sync(0xffffffffu, mx, o));
    if ((t & 31) == 0) red[t >> 5] = mx;
    __syncthreads();
    float bmx = red[0];
    #pragma unroll
    for (int i = 1; i < 8; i++) bmx = fmaxf(bmx, red[i]);
    __syncthreads();

    float s = 0.f;
    #pragma unroll
    for (int i = 0; i < 8; i++) {
        v[i] = __expf(v[i] - bmx);
        s += v[i];
    }
    #pragma unroll
    for (int o = 16; o > 0; o >>= 1) s += __shfl_xor_sync(0xffffffffu, s, o);
    if ((t & 31) == 0) red[t >> 5] = s;
    __syncthreads();
    float tot = 0.f;
    #pragma unroll
    for (int i = 0; i < 8; i++) tot += red[i];
    const float inv = 1.0f / tot;

    #pragma unroll
    for (int i = 0; i < 8; i++) {
        float val = v[i] * inv;
        p[t + i * 256] = val;
        bf16 h = __float2bfloat16(val);
        bf16 l = __float2bfloat16(val - __bfloat162float(h));
        g_Ah[gbase + t + i * 256] = h;
        g_Al[gbase + t + i * 256] = l;
    }
}

// ---------------------------------------------------------------------------
extern "C" void kernel_launch(void* const* d_in, const int* in_sizes, int n_in,
                              void* d_out, int out_size) {
    const float* Q  = (const float*)d_in[0];
    const float* K  = (const float*)d_in[1];
    const float* V  = (const float*)d_in[2];
    const float* RE = (const float*)d_in[3];

    float* attn = (float*)d_out;
    float* Z    = attn + (size_t)NB * SQL * SKL;

    bf16 *Qh, *Ql, *Kh, *Kl, *REh, *REl, *Vth, *Vtl, *Ahp, *Alp;
    float* qrel;
    cudaGetSymbolAddress((void**)&Qh,  g_Qh);
    cudaGetSymbolAddress((void**)&Ql,  g_Ql);
    cudaGetSymbolAddress((void**)&Kh,  g_Kh);
    cudaGetSymbolAddress((void**)&Kl,  g_Kl);
    cudaGetSymbolAddress((void**)&REh, g_REh);
    cudaGetSymbolAddress((void**)&REl, g_REl);
    cudaGetSymbolAddress((void**)&Vth, g_Vth);
    cudaGetSymbolAddress((void**)&Vtl, g_Vtl);
    cudaGetSymbolAddress((void**)&Ahp, g_Ah);
    cudaGetSymbolAddress((void**)&Alp, g_Al);
    cudaGetSymbolAddress((void**)&qrel, g_qrel);

    const int SMEM_GEMM = 81920;
    cudaFuncSetAttribute(mma_gemm_kernel<DIM, true>,
                         cudaFuncAttributeMaxDynamicSharedMemorySize, SMEM_GEMM);
    cudaFuncSetAttribute(mma_gemm_kernel<DIM, false>,
                         cudaFuncAttributeMaxDynamicSharedMemorySize, SMEM_GEMM);
    cudaFuncSetAttribute(mma_gemm_kernel<SKL, false>,
                         cudaFuncAttributeMaxDynamicSharedMemorySize, SMEM_GEMM);

    // splits
    split_hl_kernel<<<(NB * SQL * DIM) / 1024, 256>>>(Q, Qh, Ql);
    split_hl_kernel<<<(NB * SKL * DIM) / 1024, 256>>>(K, Kh, Kl);
    split_re_kernel<<<NRELP, 128>>>(RE, REh, REl);
    {
        dim3 grid(SKL / 32, DIM / 32, NB);
        split_v_t_kernel<<<grid, dim3(32, 8)>>>(V, Vth, Vtl);
    }
    // Q_rel = Q @ RE^T (padded to 384 cols), batch folded into M
    {
        dim3 grid((NB * SQL) / 128, NRELP / 128, 1);
        mma_gemm_kernel<DIM, false><<<grid, 256, SMEM_GEMM>>>(
            Qh, Ql, REh, REl, qrel, 0, 0, 0, NRELP);
    }
    // scores (raw energies + relpos + scale) -> attn region
    {
        dim3 grid(SQL / 128, SKL / 128, NB);
        mma_gemm_kernel<DIM, true><<<grid, 256, SMEM_GEMM>>>(
            Qh, Ql, Kh, Kl, attn,
            (size_t)SQL * DIM, (size_t)SKL * DIM, (size_t)SQL * SKL, SKL);
    }
    // softmax + split
    softmax_split_kernel<<<NB * SQL, 256>>>(attn);
    // Z = attn @ V
    {
        dim3 grid(SQL / 128, DIM / 128, NB);
        mma_gemm_kernel<SKL, false><<<grid, 256, SMEM_GEMM>>>(
            Ahp, Alp, Vth, Vtl, Z,
            (size_t)SQL * SKL, (size_t)DIM * SKL, (size_t)SQL * DIM, DIM);
    }
}